// round 1
// baseline (speedup 1.0000x reference)
#include <cuda_runtime.h>
#include <math.h>

// Problem constants
#define BB   64
#define TT   512
#define EE   300
#define HDIM 256
#define G4   1024    // 4*HDIM
#define KTAG 20

// ---------------- scratch (device globals; no runtime allocation) ----------------
__device__ float g_X[(size_t)2 * BB * TT * G4];     // pre-computed input gates (+bias), both dirs: 256MB
__device__ float g_h[(size_t)2 * BB * TT * HDIM];   // hidden states per step, both dirs: 64MB
__device__ float g_c[2 * BB * HDIM];                // cell state (current step only)
__device__ float g_emis[(size_t)BB * TT * KTAG];    // emissions

// =====================================================================
// Kernel 1: fused embedding gather + input-gate GEMM (+bias), both dirs
//   g_X[dir][b][t][j] = emb[token(dir,b,t)] . W_ih[j] + bias[j]
//   For dir=1 (backward), token index is length-reversed.
// Tiles: BM=128 x BN=64 x BK=16, 256 threads, 8x4 per-thread microtile.
// =====================================================================
#define BM 128
#define BN 64
#define BK 16

__global__ void gates_gemm_kernel(const int* __restrict__ sentence,
                                  const int* __restrict__ lengths,
                                  const float* __restrict__ emb,
                                  const float* __restrict__ Wf_ih,
                                  const float* __restrict__ bf,
                                  const float* __restrict__ Wb_ih,
                                  const float* __restrict__ bb)
{
    const int dir = blockIdx.z;
    const int m0  = blockIdx.x * BM;   // row block (b*512+t), fully inside one b
    const int n0  = blockIdx.y * BN;   // gate-column block
    const float* __restrict__ W    = dir ? Wb_ih : Wf_ih;
    const float* __restrict__ bias = dir ? bb    : bf;

    __shared__ float As[BM][BK + 1];
    __shared__ float Bs[BK][BN + 4];
    __shared__ int   tok[BM];

    const int tid = threadIdx.x;
    const int b   = m0 / TT;

    if (tid < BM) {
        int t = (m0 + tid) % TT;
        if (dir) {
            int len = lengths[b];
            t = (t < len) ? (len - 1 - t) : t;
        }
        tok[tid] = sentence[b * TT + t];
    }
    __syncthreads();

    float acc[8][4];
#pragma unroll
    for (int i = 0; i < 8; i++)
#pragma unroll
        for (int j = 0; j < 4; j++) acc[i][j] = 0.f;

    const int tx = tid & 15;   // N dim (x4)
    const int ty = tid >> 4;   // M dim (x8)

    for (int k0 = 0; k0 < 304; k0 += BK) {
        // load A tile: 128x16 gathered embedding rows
        {
            const int ar = tid >> 1;
            const int ac = (tid & 1) * 8;
            const float* erow = emb + (size_t)tok[ar] * EE;
#pragma unroll
            for (int i = 0; i < 8; i++) {
                int k = k0 + ac + i;
                As[ar][ac + i] = (k < EE) ? erow[k] : 0.f;
            }
        }
        // load B tile: W_ih[n][k] transposed into Bs[k][n]
        {
            const int bn = tid >> 2;
            const int bk = (tid & 3) * 4;
            const float* wrow = W + (size_t)(n0 + bn) * EE;
#pragma unroll
            for (int i = 0; i < 4; i++) {
                int k = k0 + bk + i;
                Bs[bk + i][bn] = (k < EE) ? wrow[k] : 0.f;
            }
        }
        __syncthreads();

#pragma unroll
        for (int kk = 0; kk < BK; kk++) {
            float a[8];
#pragma unroll
            for (int i = 0; i < 8; i++) a[i] = As[ty * 8 + i][kk];
            float4 bv = *(const float4*)&Bs[kk][tx * 4];
#pragma unroll
            for (int i = 0; i < 8; i++) {
                acc[i][0] += a[i] * bv.x;
                acc[i][1] += a[i] * bv.y;
                acc[i][2] += a[i] * bv.z;
                acc[i][3] += a[i] * bv.w;
            }
        }
        __syncthreads();
    }

    // epilogue: add bias, store
    float4 bv;
    bv.x = bias[n0 + tx * 4 + 0];
    bv.y = bias[n0 + tx * 4 + 1];
    bv.z = bias[n0 + tx * 4 + 2];
    bv.w = bias[n0 + tx * 4 + 3];
#pragma unroll
    for (int i = 0; i < 8; i++) {
        size_t m = (size_t)m0 + ty * 8 + i;
        float4 v;
        v.x = acc[i][0] + bv.x;
        v.y = acc[i][1] + bv.y;
        v.z = acc[i][2] + bv.z;
        v.w = acc[i][3] + bv.w;
        *(float4*)&g_X[((size_t)dir * BB * TT + m) * G4 + n0 + tx * 4] = v;
    }
}

// =====================================================================
// Kernel 2: one LSTM time step, both directions.
// 128 CTAs: (dir:2) x (k-slice of 32: 8) x (batch tile of 8: 8)
// 256 threads = 8 batch x 32 k. Each thread computes gates i,f,g,o for
// its (b,k) via 4 dot products over h_prev (smem) x W_hh rows (L2),
// then the pointwise cell/hidden update.
// =====================================================================
__device__ __forceinline__ float sigf(float x) { return 1.f / (1.f + expf(-x)); }

__global__ void lstm_step_kernel(const float* __restrict__ Wf_hh,
                                 const float* __restrict__ Wb_hh, int t)
{
    const int bx  = blockIdx.x;
    const int dir = bx & 1;
    const int ks  = (bx >> 1) & 7;
    const int bt  = bx >> 4;
    const int k0  = ks * 32;
    const int b0  = bt * 8;
    const float* __restrict__ W = dir ? Wb_hh : Wf_hh;

    __shared__ float hs[8][260];   // pad 260: conflict-free + float4 aligned

    const int tid = threadIdx.x;
    {
        const int row = tid >> 5;          // 0..7
        const int c0  = (tid & 31) * 8;    // 0..248
        float4 v0, v1;
        if (t == 0) {
            v0 = make_float4(0.f, 0.f, 0.f, 0.f); v1 = v0;
        } else {
            const float* src = g_h + (((size_t)dir * BB + b0 + row) * TT + (t - 1)) * HDIM + c0;
            v0 = *(const float4*)src;
            v1 = *(const float4*)(src + 4);
        }
        *(float4*)&hs[row][c0]     = v0;
        *(float4*)&hs[row][c0 + 4] = v1;
    }
    __syncthreads();

    const int b_l = tid & 7;
    const int k_l = tid >> 3;
    const int k = k0 + k_l;
    const int b = b0 + b_l;

    const float* __restrict__ xr = g_X + (((size_t)dir * BB + b) * TT + t) * G4;
    float ai = xr[k];
    float af = xr[HDIM + k];
    float ag = xr[2 * HDIM + k];
    float ao = xr[3 * HDIM + k];

    const float* __restrict__ wi = W + (size_t)k * HDIM;
    const float* __restrict__ wf = W + (size_t)(HDIM + k) * HDIM;
    const float* __restrict__ wg = W + (size_t)(2 * HDIM + k) * HDIM;
    const float* __restrict__ wo = W + (size_t)(3 * HDIM + k) * HDIM;
    const float* hr = hs[b_l];

#pragma unroll 4
    for (int kk = 0; kk < HDIM; kk += 4) {
        float4 h4 = *(const float4*)(hr + kk);
        float4 w1 = *(const float4*)(wi + kk);
        float4 w2 = *(const float4*)(wf + kk);
        float4 w3 = *(const float4*)(wg + kk);
        float4 w4 = *(const float4*)(wo + kk);
        ai += h4.x * w1.x + h4.y * w1.y + h4.z * w1.z + h4.w * w1.w;
        af += h4.x * w2.x + h4.y * w2.y + h4.z * w2.z + h4.w * w2.w;
        ag += h4.x * w3.x + h4.y * w3.y + h4.z * w3.z + h4.w * w3.w;
        ao += h4.x * w4.x + h4.y * w4.y + h4.z * w4.z + h4.w * w4.w;
    }

    const size_t cidx = ((size_t)dir * BB + b) * HDIM + k;
    float c_old = (t == 0) ? 0.f : g_c[cidx];
    float cn = sigf(af) * c_old + sigf(ai) * tanhf(ag);
    float hn = sigf(ao) * tanhf(cn);
    g_c[cidx] = cn;
    g_h[(((size_t)dir * BB + b) * TT + t) * HDIM + k] = hn;
}

// =====================================================================
// Kernel 3: emissions = concat(hf, hb_rev_reversed_back) @ W_out^T + b_out
// One warp per (b,t) token; 8 warps per block.
// =====================================================================
__global__ void emis_kernel(const int* __restrict__ lengths,
                            const float* __restrict__ W_out,
                            const float* __restrict__ b_out)
{
    const int warp = threadIdx.x >> 5;
    const int lane = threadIdx.x & 31;
    const int r = blockIdx.x * 8 + warp;      // 0..32767
    const int b = r >> 9;
    const int t = r & 511;
    const int len = lengths[b];
    const int tr  = (t < len) ? (len - 1 - t) : t;

    const float* hf = g_h + (((size_t)0 * BB + b) * TT + t)  * HDIM;
    const float* hb = g_h + (((size_t)1 * BB + b) * TT + tr) * HDIM;

    float x[16];
#pragma unroll
    for (int i = 0; i < 8; i++) x[i]     = hf[lane + 32 * i];
#pragma unroll
    for (int i = 0; i < 8; i++) x[8 + i] = hb[lane + 32 * i];

    for (int kk = 0; kk < KTAG; kk++) {
        const float* w = W_out + (size_t)kk * (2 * HDIM);
        float s = 0.f;
#pragma unroll
        for (int i = 0; i < 8; i++) s += x[i]     * w[lane + 32 * i];
#pragma unroll
        for (int i = 0; i < 8; i++) s += x[8 + i] * w[HDIM + lane + 32 * i];
#pragma unroll
        for (int off = 16; off; off >>= 1) s += __shfl_xor_sync(0xffffffffu, s, off);
        if (lane == 0) g_emis[((size_t)b * TT + t) * KTAG + kk] = s + b_out[kk];
    }
}

// =====================================================================
// Kernel 4: Viterbi DP + backtrace. One block (32 threads) per batch.
// Matches jnp.argmax first-max semantics (strict '>' on ascending scan).
// =====================================================================
__global__ void viterbi_kernel(const int* __restrict__ lengths,
                               const int* __restrict__ stop_id_p,
                               const float* __restrict__ trans,
                               float* __restrict__ out)
{
    const int b = blockIdx.x;
    const int lane = threadIdx.x;

    __shared__ float tr[KTAG][KTAG];
    __shared__ float delta[KTAG];
    __shared__ float term[KTAG];
    __shared__ unsigned char bp[TT][KTAG];

    for (int i = lane; i < KTAG * KTAG; i += 32) tr[i / KTAG][i % KTAG] = trans[i];
    if (lane < KTAG) delta[lane] = 0.f;
    __syncwarp();

    const int len  = lengths[b];
    const int stop = *stop_id_p;

    for (int t = 0; t < TT; t++) {
        float nd = 0.f; int bpv = 0;
        if (lane < KTAG) {
            if (t < len) {
                float best = -3.4e38f; int arg = 0;
#pragma unroll
                for (int p = 0; p < KTAG; p++) {
                    float s = delta[p] + tr[lane][p];
                    if (s > best) { best = s; arg = p; }
                }
                nd  = best + g_emis[((size_t)b * TT + t) * KTAG + lane];
                bpv = arg;
            } else {
                nd  = delta[lane];
                bpv = lane;
            }
        }
        __syncwarp();
        if (lane < KTAG) { delta[lane] = nd; bp[t][lane] = (unsigned char)bpv; }
        __syncwarp();
    }

    if (lane < KTAG) term[lane] = delta[lane] + tr[stop][lane];
    __syncwarp();

    if (lane == 0) {
        float best = -3.4e38f; int arg = 0;
        for (int j = 0; j < KTAG; j++)
            if (term[j] > best) { best = term[j]; arg = j; }
        out[b] = best;                               // scores[b]
        float* po = out + BB + (size_t)b * (TT + 1); // paths row
        po[TT] = (float)arg;
        int tag = arg;
        for (int t = TT - 1; t >= 0; t--) {
            tag = bp[t][tag];
            po[t] = (float)tag;
        }
    }
}

// =====================================================================
// launch
// =====================================================================
extern "C" void kernel_launch(void* const* d_in, const int* in_sizes, int n_in,
                              void* d_out, int out_size)
{
    (void)in_sizes; (void)n_in; (void)out_size;
    const int*   sentence = (const int*)d_in[0];
    const int*   lengths  = (const int*)d_in[1];
    /* d_in[2] = start_id (unused) */
    const int*   stop_id  = (const int*)d_in[3];
    const float* emb      = (const float*)d_in[4];
    const float* Wf_ih    = (const float*)d_in[5];
    const float* Wf_hh    = (const float*)d_in[6];
    const float* bf       = (const float*)d_in[7];
    const float* Wb_ih    = (const float*)d_in[8];
    const float* Wb_hh    = (const float*)d_in[9];
    const float* bb       = (const float*)d_in[10];
    const float* W_out    = (const float*)d_in[11];
    const float* b_out    = (const float*)d_in[12];
    const float* trans    = (const float*)d_in[13];
    float* out = (float*)d_out;

    dim3 g1(BB * TT / BM, G4 / BN, 2);   // 256 x 16 x 2
    gates_gemm_kernel<<<g1, 256>>>(sentence, lengths, emb, Wf_ih, bf, Wb_ih, bb);

    for (int t = 0; t < TT; t++)
        lstm_step_kernel<<<128, 256>>>(Wf_hh, Wb_hh, t);

    emis_kernel<<<BB * TT / 8, 256>>>(lengths, W_out, b_out);

    viterbi_kernel<<<BB, 32>>>(lengths, stop_id, trans, out);
}

// round 2
// speedup vs baseline: 1.5604x; 1.5604x over previous
#include <cuda_runtime.h>
#include <math.h>

// Problem constants
#define BB   64
#define TT   512
#define EE   300
#define HDIM 256
#define G4   1024    // 4*HDIM
#define KTAG 20
#define GRID_P 128   // persistent CTAs (<=148 SMs -> co-resident)

// ---------------- scratch (device globals; no runtime allocation) ----------------
__device__ float g_X[(size_t)2 * BB * TT * G4];     // input-gate preactivations (+bias), both dirs
__device__ float g_h[(size_t)2 * BB * TT * HDIM];   // hidden states per step, both dirs
__device__ float g_emis[(size_t)BB * TT * KTAG];    // emissions
__device__ int           g_count;                   // grid-barrier arrival counter (self-resetting)
__device__ volatile int  g_flag;                    // grid-barrier phase flag (monotone)

// =====================================================================
// Kernel 1: fused embedding gather + input-gate GEMM (+bias), both dirs
// =====================================================================
#define BM 128
#define BN 64
#define BK 16

__global__ void gates_gemm_kernel(const int* __restrict__ sentence,
                                  const int* __restrict__ lengths,
                                  const float* __restrict__ emb,
                                  const float* __restrict__ Wf_ih,
                                  const float* __restrict__ bf,
                                  const float* __restrict__ Wb_ih,
                                  const float* __restrict__ bb)
{
    const int dir = blockIdx.z;
    const int m0  = blockIdx.x * BM;
    const int n0  = blockIdx.y * BN;
    const float* __restrict__ W    = dir ? Wb_ih : Wf_ih;
    const float* __restrict__ bias = dir ? bb    : bf;

    __shared__ float As[BM][BK + 1];
    __shared__ float Bs[BK][BN + 4];
    __shared__ int   tok[BM];

    const int tid = threadIdx.x;
    const int b   = m0 / TT;

    if (tid < BM) {
        int t = (m0 + tid) % TT;
        if (dir) {
            int len = lengths[b];
            t = (t < len) ? (len - 1 - t) : t;
        }
        tok[tid] = sentence[b * TT + t];
    }
    __syncthreads();

    float acc[8][4];
#pragma unroll
    for (int i = 0; i < 8; i++)
#pragma unroll
        for (int j = 0; j < 4; j++) acc[i][j] = 0.f;

    const int tx = tid & 15;
    const int ty = tid >> 4;

    for (int k0 = 0; k0 < 304; k0 += BK) {
        {
            const int ar = tid >> 1;
            const int ac = (tid & 1) * 8;
            const float* erow = emb + (size_t)tok[ar] * EE;
#pragma unroll
            for (int i = 0; i < 8; i++) {
                int k = k0 + ac + i;
                As[ar][ac + i] = (k < EE) ? erow[k] : 0.f;
            }
        }
        {
            const int bn = tid >> 2;
            const int bk = (tid & 3) * 4;
            const float* wrow = W + (size_t)(n0 + bn) * EE;
#pragma unroll
            for (int i = 0; i < 4; i++) {
                int k = k0 + bk + i;
                Bs[bk + i][bn] = (k < EE) ? wrow[k] : 0.f;
            }
        }
        __syncthreads();

#pragma unroll
        for (int kk = 0; kk < BK; kk++) {
            float a[8];
#pragma unroll
            for (int i = 0; i < 8; i++) a[i] = As[ty * 8 + i][kk];
            float4 bv = *(const float4*)&Bs[kk][tx * 4];
#pragma unroll
            for (int i = 0; i < 8; i++) {
                acc[i][0] += a[i] * bv.x;
                acc[i][1] += a[i] * bv.y;
                acc[i][2] += a[i] * bv.z;
                acc[i][3] += a[i] * bv.w;
            }
        }
        __syncthreads();
    }

    float4 bv;
    bv.x = bias[n0 + tx * 4 + 0];
    bv.y = bias[n0 + tx * 4 + 1];
    bv.z = bias[n0 + tx * 4 + 2];
    bv.w = bias[n0 + tx * 4 + 3];
#pragma unroll
    for (int i = 0; i < 8; i++) {
        size_t m = (size_t)m0 + ty * 8 + i;
        float4 v;
        v.x = acc[i][0] + bv.x;
        v.y = acc[i][1] + bv.y;
        v.z = acc[i][2] + bv.z;
        v.w = acc[i][3] + bv.w;
        *(float4*)&g_X[((size_t)dir * BB * TT + m) * G4 + n0 + tx * 4] = v;
    }
}

// =====================================================================
// Kernel 2: PERSISTENT bidirectional LSTM.
// 128 CTAs: (dir:2) x (k-slice of 32: 8) x (batch tile of 8: 8), co-resident.
// W_hh slice cached in smem once; c in registers; custom grid barrier/step;
// X(t+1) prefetched before the barrier to hide both latencies.
// =====================================================================
#define WS_STRIDE 264              // 1056B row: 4 rows land on distinct bank phases
#define HS_STRIDE 260              // 1040B row: 8 rows land on distinct bank phases
#define SMEM_LSTM ((4 * 32 * WS_STRIDE + 8 * HS_STRIDE) * 4)

__device__ __forceinline__ float sigf(float x) { return 1.f / (1.f + expf(-x)); }

__global__ void lstm_persistent_kernel(const float* __restrict__ Wf_hh,
                                       const float* __restrict__ Wb_hh)
{
    extern __shared__ float sm[];
    float* Ws  = sm;                       // [4*32][WS_STRIDE]
    float* hsm = sm + 4 * 32 * WS_STRIDE;  // [8][HS_STRIDE]

    const int bx  = blockIdx.x;
    const int dir = bx & 1;
    const int ks  = (bx >> 1) & 7;
    const int bt  = bx >> 4;
    const int k0  = ks * 32;
    const int b0  = bt * 8;
    const int tid = threadIdx.x;
    const float* __restrict__ W = dir ? Wb_hh : Wf_hh;

    // cooperative load of W slice into smem (once)
    for (int i = tid; i < 128 * 64; i += 256) {
        int r = i >> 6;                    // gate*32 + k_l
        int c = (i & 63) * 4;
        int gate = r >> 5, k_l = r & 31;
        float4 v = *(const float4*)(W + ((size_t)(gate * 256 + k0 + k_l)) * HDIM + c);
        *(float4*)(Ws + (size_t)r * WS_STRIDE + c) = v;
    }
    for (int i = tid; i < 8 * HS_STRIDE; i += 256) hsm[i] = 0.f;

    const int base = g_flag;               // stable: flag can't advance until all CTAs arrive
    __syncthreads();

    const int b_l = tid & 7, k_l = tid >> 3;
    const int b = b0 + b_l, k = k0 + k_l;
    const float* hr = hsm + b_l * HS_STRIDE;
    const float* wi = Ws + (size_t)(0 * 32 + k_l) * WS_STRIDE;
    const float* wf = Ws + (size_t)(1 * 32 + k_l) * WS_STRIDE;
    const float* wg = Ws + (size_t)(2 * 32 + k_l) * WS_STRIDE;
    const float* wo = Ws + (size_t)(3 * 32 + k_l) * WS_STRIDE;
    const float* xbase   = g_X + (((size_t)dir * BB + b) * TT) * G4 + k;
    float*       houtb   = g_h + (((size_t)dir * BB + b) * TT) * HDIM + k;

    // hsm reload mapping (for next step): 8 rows x 256 cols
    const int lrow = tid >> 5, lc0 = (tid & 31) * 8;
    const float* hsrcb = g_h + (((size_t)dir * BB + b0 + lrow) * TT) * HDIM + lc0;

    float c_st = 0.f;
    // prefetch X for t=0
    float xi = xbase[0], xf = xbase[256], xg = xbase[512], xo = xbase[768];

    for (int t = 0; t < TT; t++) {
        float ai0 = 0.f, ai1 = 0.f, af0 = 0.f, af1 = 0.f;
        float ag0 = 0.f, ag1 = 0.f, ao0 = 0.f, ao1 = 0.f;

#pragma unroll 4
        for (int kk = 0; kk < HDIM; kk += 8) {
            float4 ha = *(const float4*)(hr + kk);
            float4 hb = *(const float4*)(hr + kk + 4);
            float4 w;
            w = *(const float4*)(wi + kk);     ai0 += ha.x*w.x + ha.y*w.y + ha.z*w.z + ha.w*w.w;
            w = *(const float4*)(wi + kk + 4); ai1 += hb.x*w.x + hb.y*w.y + hb.z*w.z + hb.w*w.w;
            w = *(const float4*)(wf + kk);     af0 += ha.x*w.x + ha.y*w.y + ha.z*w.z + ha.w*w.w;
            w = *(const float4*)(wf + kk + 4); af1 += hb.x*w.x + hb.y*w.y + hb.z*w.z + hb.w*w.w;
            w = *(const float4*)(wg + kk);     ag0 += ha.x*w.x + ha.y*w.y + ha.z*w.z + ha.w*w.w;
            w = *(const float4*)(wg + kk + 4); ag1 += hb.x*w.x + hb.y*w.y + hb.z*w.z + hb.w*w.w;
            w = *(const float4*)(wo + kk);     ao0 += ha.x*w.x + ha.y*w.y + ha.z*w.z + ha.w*w.w;
            w = *(const float4*)(wo + kk + 4); ao1 += hb.x*w.x + hb.y*w.y + hb.z*w.z + hb.w*w.w;
        }

        float gi = xi + ai0 + ai1;
        float gf = xf + af0 + af1;
        float gg = xg + ag0 + ag1;
        float go = xo + ao0 + ao1;

        c_st = sigf(gf) * c_st + sigf(gi) * tanhf(gg);
        float hn = sigf(go) * tanhf(c_st);
        houtb[(size_t)t * HDIM] = hn;

        // prefetch X(t+1) while the barrier drains
        if (t + 1 < TT) {
            const float* xr = xbase + (size_t)(t + 1) * G4;
            xi = xr[0]; xf = xr[256]; xg = xr[512]; xo = xr[768];
        }

        if (t + 1 < TT) {
            __threadfence();               // publish h(t) before arriving
            __syncthreads();
            if (tid == 0) {
                int target = base + t + 1;
                int prev = atomicAdd(&g_count, 1);
                if (prev == GRID_P - 1) {
                    g_count = 0;
                    __threadfence();
                    g_flag = target;
                } else {
                    while (g_flag < target) { }
                }
                __threadfence();           // acquire peers' h(t)
            }
            __syncthreads();

            // reload h(t) for my 8 batches, all 256 k
            const float* src = hsrcb + (size_t)t * HDIM;
            float4 v0 = *(const float4*)src;
            float4 v1 = *(const float4*)(src + 4);
            *(float4*)(hsm + lrow * HS_STRIDE + lc0)     = v0;
            *(float4*)(hsm + lrow * HS_STRIDE + lc0 + 4) = v1;
            __syncthreads();
        }
    }
}

// =====================================================================
// Kernel 3: emissions
// =====================================================================
__global__ void emis_kernel(const int* __restrict__ lengths,
                            const float* __restrict__ W_out,
                            const float* __restrict__ b_out)
{
    const int warp = threadIdx.x >> 5;
    const int lane = threadIdx.x & 31;
    const int r = blockIdx.x * 8 + warp;
    const int b = r >> 9;
    const int t = r & 511;
    const int len = lengths[b];
    const int tr  = (t < len) ? (len - 1 - t) : t;

    const float* hf = g_h + (((size_t)0 * BB + b) * TT + t)  * HDIM;
    const float* hb = g_h + (((size_t)1 * BB + b) * TT + tr) * HDIM;

    float x[16];
#pragma unroll
    for (int i = 0; i < 8; i++) x[i]     = hf[lane + 32 * i];
#pragma unroll
    for (int i = 0; i < 8; i++) x[8 + i] = hb[lane + 32 * i];

    for (int kk = 0; kk < KTAG; kk++) {
        const float* w = W_out + (size_t)kk * (2 * HDIM);
        float s = 0.f;
#pragma unroll
        for (int i = 0; i < 8; i++) s += x[i]     * w[lane + 32 * i];
#pragma unroll
        for (int i = 0; i < 8; i++) s += x[8 + i] * w[HDIM + lane + 32 * i];
#pragma unroll
        for (int off = 16; off; off >>= 1) s += __shfl_xor_sync(0xffffffffu, s, off);
        if (lane == 0) g_emis[((size_t)b * TT + t) * KTAG + kk] = s + b_out[kk];
    }
}

// =====================================================================
// Kernel 4: Viterbi DP + backtrace (jnp.argmax first-max semantics)
// =====================================================================
__global__ void viterbi_kernel(const int* __restrict__ lengths,
                               const int* __restrict__ stop_id_p,
                               const float* __restrict__ trans,
                               float* __restrict__ out)
{
    const int b = blockIdx.x;
    const int lane = threadIdx.x;

    __shared__ float tr[KTAG][KTAG];
    __shared__ float delta[KTAG];
    __shared__ float term[KTAG];
    __shared__ unsigned char bp[TT][KTAG];

    for (int i = lane; i < KTAG * KTAG; i += 32) tr[i / KTAG][i % KTAG] = trans[i];
    if (lane < KTAG) delta[lane] = 0.f;
    __syncwarp();

    const int len  = lengths[b];
    const int stop = *stop_id_p;

    for (int t = 0; t < TT; t++) {
        float nd = 0.f; int bpv = 0;
        if (lane < KTAG) {
            if (t < len) {
                float best = -3.4e38f; int arg = 0;
#pragma unroll
                for (int p = 0; p < KTAG; p++) {
                    float s = delta[p] + tr[lane][p];
                    if (s > best) { best = s; arg = p; }
                }
                nd  = best + g_emis[((size_t)b * TT + t) * KTAG + lane];
                bpv = arg;
            } else {
                nd  = delta[lane];
                bpv = lane;
            }
        }
        __syncwarp();
        if (lane < KTAG) { delta[lane] = nd; bp[t][lane] = (unsigned char)bpv; }
        __syncwarp();
    }

    if (lane < KTAG) term[lane] = delta[lane] + tr[stop][lane];
    __syncwarp();

    if (lane == 0) {
        float best = -3.4e38f; int arg = 0;
        for (int j = 0; j < KTAG; j++)
            if (term[j] > best) { best = term[j]; arg = j; }
        out[b] = best;
        float* po = out + BB + (size_t)b * (TT + 1);
        po[TT] = (float)arg;
        int tag = arg;
        for (int t = TT - 1; t >= 0; t--) {
            tag = bp[t][tag];
            po[t] = (float)tag;
        }
    }
}

// =====================================================================
// launch
// =====================================================================
extern "C" void kernel_launch(void* const* d_in, const int* in_sizes, int n_in,
                              void* d_out, int out_size)
{
    (void)in_sizes; (void)n_in; (void)out_size;
    const int*   sentence = (const int*)d_in[0];
    const int*   lengths  = (const int*)d_in[1];
    const int*   stop_id  = (const int*)d_in[3];
    const float* emb      = (const float*)d_in[4];
    const float* Wf_ih    = (const float*)d_in[5];
    const float* Wf_hh    = (const float*)d_in[6];
    const float* bf       = (const float*)d_in[7];
    const float* Wb_ih    = (const float*)d_in[8];
    const float* Wb_hh    = (const float*)d_in[9];
    const float* bb       = (const float*)d_in[10];
    const float* W_out    = (const float*)d_in[11];
    const float* b_out    = (const float*)d_in[12];
    const float* trans    = (const float*)d_in[13];
    float* out = (float*)d_out;

    static int smem_set = 0;
    if (!smem_set) {
        cudaFuncSetAttribute(lstm_persistent_kernel,
                             cudaFuncAttributeMaxDynamicSharedMemorySize, SMEM_LSTM);
        smem_set = 1;
    }

    dim3 g1(BB * TT / BM, G4 / BN, 2);
    gates_gemm_kernel<<<g1, 256>>>(sentence, lengths, emb, Wf_ih, bf, Wb_ih, bb);

    lstm_persistent_kernel<<<GRID_P, 256, SMEM_LSTM>>>(Wf_hh, Wb_hh);

    emis_kernel<<<BB * TT / 8, 256>>>(lengths, W_out, b_out);

    viterbi_kernel<<<BB, 32>>>(lengths, stop_id, trans, out);
}

// round 3
// speedup vs baseline: 1.5713x; 1.0070x over previous
#include <cuda_runtime.h>
#include <math.h>

// Problem constants
#define BB   64
#define TT   512
#define EE   300
#define HDIM 256
#define G4   1024    // 4*HDIM
#define KTAG 20
#define GRID_P 128   // persistent CTAs (<=148 SMs -> co-resident)

typedef unsigned long long ull;

// ---------------- scratch (device globals; no runtime allocation) ----------------
__device__ float g_X[(size_t)2 * BB * TT * G4];     // input-gate preactivations (+bias), both dirs
__device__ float g_h[(size_t)2 * BB * TT * HDIM];   // hidden states per step, both dirs
__device__ float g_emis[(size_t)BB * TT * KTAG];    // emissions
__device__ int           g_count;                   // grid-barrier arrival counter (self-resetting)
__device__ volatile int  g_flag;                    // grid-barrier phase flag (monotone)

// ---------------- packed fp32x2 helpers (sm_103a FFMA2) ----------------
__device__ __forceinline__ ull ffma2(ull a, ull b, ull c) {
    ull d;
    asm("fma.rn.f32x2 %0, %1, %2, %3;" : "=l"(d) : "l"(a), "l"(b), "l"(c));
    return d;
}
__device__ __forceinline__ ull f2u2(float x, float y) {
    ull v;
    asm("mov.b64 %0, {%1, %2};" : "=l"(v) : "f"(x), "f"(y));
    return v;
}
__device__ __forceinline__ float2 u2f2(ull v) {
    float2 f;
    asm("mov.b64 {%0, %1}, %2;" : "=f"(f.x), "=f"(f.y) : "l"(v));
    return f;
}

// =====================================================================
// Kernel 1: fused embedding gather + input-gate GEMM (+bias), both dirs
// As stored [BK][BM] so the 8-row microtile is pre-packed f32x2 pairs.
// 16 FFMA2 per kk per thread (8m x 4n microtile).
// =====================================================================
#define BM 128
#define BN 64
#define BK 16

__global__ void gates_gemm_kernel(const int* __restrict__ sentence,
                                  const int* __restrict__ lengths,
                                  const float* __restrict__ emb,
                                  const float* __restrict__ Wf_ih,
                                  const float* __restrict__ bf,
                                  const float* __restrict__ Wb_ih,
                                  const float* __restrict__ bb)
{
    const int dir = blockIdx.z;
    const int m0  = blockIdx.x * BM;
    const int n0  = blockIdx.y * BN;
    const float* __restrict__ W    = dir ? Wb_ih : Wf_ih;
    const float* __restrict__ bias = dir ? bb    : bf;

    __shared__ float As[BK][BM + 4];   // [k][m] layout, stride 132 (528B, 16B-mult)
    __shared__ float Bs[BK][BN + 4];   // [k][n]
    __shared__ int   tok[BM];

    const int tid = threadIdx.x;
    const int b   = m0 / TT;

    if (tid < BM) {
        int t = (m0 + tid) % TT;
        if (dir) {
            int len = lengths[b];
            t = (t < len) ? (len - 1 - t) : t;
        }
        tok[tid] = sentence[b * TT + t];
    }
    __syncthreads();

    ull acc[4][4];   // [m-pair][n], each packs rows (2mp, 2mp+1)
#pragma unroll
    for (int i = 0; i < 4; i++)
#pragma unroll
        for (int j = 0; j < 4; j++) acc[i][j] = 0ull;

    const int tx = tid & 15;   // n (x4)
    const int ty = tid >> 4;   // m (x8)

    for (int k0 = 0; k0 < 304; k0 += BK) {
        // A tile: gathered embedding rows -> As[k][m]
        {
            const int ar = tid >> 1;
            const int ac = (tid & 1) * 8;
            const float* erow = emb + (size_t)tok[ar] * EE;
#pragma unroll
            for (int i = 0; i < 8; i++) {
                int k = k0 + ac + i;
                As[ac + i][ar] = (k < EE) ? erow[k] : 0.f;
            }
        }
        // B tile: W_ih[n][k] -> Bs[k][n]
        {
            const int bn = tid >> 2;
            const int bk = (tid & 3) * 4;
            const float* wrow = W + (size_t)(n0 + bn) * EE;
#pragma unroll
            for (int i = 0; i < 4; i++) {
                int k = k0 + bk + i;
                Bs[bk + i][bn] = (k < EE) ? wrow[k] : 0.f;
            }
        }
        __syncthreads();

#pragma unroll
        for (int kk = 0; kk < BK; kk++) {
            ulonglong2 a0 = *(const ulonglong2*)&As[kk][ty * 8];      // rows 0-3
            ulonglong2 a1 = *(const ulonglong2*)&As[kk][ty * 8 + 4];  // rows 4-7
            float4 bv = *(const float4*)&Bs[kk][tx * 4];
            ull b0 = f2u2(bv.x, bv.x);
            ull b1 = f2u2(bv.y, bv.y);
            ull b2 = f2u2(bv.z, bv.z);
            ull b3 = f2u2(bv.w, bv.w);
            acc[0][0] = ffma2(a0.x, b0, acc[0][0]);
            acc[0][1] = ffma2(a0.x, b1, acc[0][1]);
            acc[0][2] = ffma2(a0.x, b2, acc[0][2]);
            acc[0][3] = ffma2(a0.x, b3, acc[0][3]);
            acc[1][0] = ffma2(a0.y, b0, acc[1][0]);
            acc[1][1] = ffma2(a0.y, b1, acc[1][1]);
            acc[1][2] = ffma2(a0.y, b2, acc[1][2]);
            acc[1][3] = ffma2(a0.y, b3, acc[1][3]);
            acc[2][0] = ffma2(a1.x, b0, acc[2][0]);
            acc[2][1] = ffma2(a1.x, b1, acc[2][1]);
            acc[2][2] = ffma2(a1.x, b2, acc[2][2]);
            acc[2][3] = ffma2(a1.x, b3, acc[2][3]);
            acc[3][0] = ffma2(a1.y, b0, acc[3][0]);
            acc[3][1] = ffma2(a1.y, b1, acc[3][1]);
            acc[3][2] = ffma2(a1.y, b2, acc[3][2]);
            acc[3][3] = ffma2(a1.y, b3, acc[3][3]);
        }
        __syncthreads();
    }

    float4 bv;
    bv.x = bias[n0 + tx * 4 + 0];
    bv.y = bias[n0 + tx * 4 + 1];
    bv.z = bias[n0 + tx * 4 + 2];
    bv.w = bias[n0 + tx * 4 + 3];
#pragma unroll
    for (int mp = 0; mp < 4; mp++) {
        float2 c0 = u2f2(acc[mp][0]);
        float2 c1 = u2f2(acc[mp][1]);
        float2 c2 = u2f2(acc[mp][2]);
        float2 c3 = u2f2(acc[mp][3]);
        size_t mA = (size_t)m0 + ty * 8 + 2 * mp;
        float4 vA, vB;
        vA.x = c0.x + bv.x; vA.y = c1.x + bv.y; vA.z = c2.x + bv.z; vA.w = c3.x + bv.w;
        vB.x = c0.y + bv.x; vB.y = c1.y + bv.y; vB.z = c2.y + bv.z; vB.w = c3.y + bv.w;
        *(float4*)&g_X[((size_t)dir * BB * TT + mA)     * G4 + n0 + tx * 4] = vA;
        *(float4*)&g_X[((size_t)dir * BB * TT + mA + 1) * G4 + n0 + tx * 4] = vB;
    }
}

// =====================================================================
// Kernel 2: PERSISTENT bidirectional LSTM, FFMA2 mainloop.
// =====================================================================
#define WS_STRIDE 264
#define HS_STRIDE 260
#define SMEM_LSTM ((4 * 32 * WS_STRIDE + 8 * HS_STRIDE) * 4)

__device__ __forceinline__ float sigf(float x) { return 1.f / (1.f + expf(-x)); }

__global__ void lstm_persistent_kernel(const float* __restrict__ Wf_hh,
                                       const float* __restrict__ Wb_hh)
{
    extern __shared__ float sm[];
    float* Ws  = sm;                       // [4*32][WS_STRIDE]
    float* hsm = sm + 4 * 32 * WS_STRIDE;  // [8][HS_STRIDE]

    const int bx  = blockIdx.x;
    const int dir = bx & 1;
    const int ks  = (bx >> 1) & 7;
    const int bt  = bx >> 4;
    const int k0  = ks * 32;
    const int b0  = bt * 8;
    const int tid = threadIdx.x;
    const float* __restrict__ W = dir ? Wb_hh : Wf_hh;

    for (int i = tid; i < 128 * 64; i += 256) {
        int r = i >> 6;
        int c = (i & 63) * 4;
        int gate = r >> 5, k_l = r & 31;
        float4 v = *(const float4*)(W + ((size_t)(gate * 256 + k0 + k_l)) * HDIM + c);
        *(float4*)(Ws + (size_t)r * WS_STRIDE + c) = v;
    }
    for (int i = tid; i < 8 * HS_STRIDE; i += 256) hsm[i] = 0.f;

    const int base = g_flag;
    __syncthreads();

    const int b_l = tid & 7, k_l = tid >> 3;
    const int b = b0 + b_l, k = k0 + k_l;
    const float* hr = hsm + b_l * HS_STRIDE;
    const float* wi = Ws + (size_t)(0 * 32 + k_l) * WS_STRIDE;
    const float* wf = Ws + (size_t)(1 * 32 + k_l) * WS_STRIDE;
    const float* wg = Ws + (size_t)(2 * 32 + k_l) * WS_STRIDE;
    const float* wo = Ws + (size_t)(3 * 32 + k_l) * WS_STRIDE;
    const float* xbase = g_X + (((size_t)dir * BB + b) * TT) * G4 + k;
    float*       houtb = g_h + (((size_t)dir * BB + b) * TT) * HDIM + k;

    const int lrow = tid >> 5, lc0 = (tid & 31) * 8;
    const float* hsrcb = g_h + (((size_t)dir * BB + b0 + lrow) * TT) * HDIM + lc0;

    float c_st = 0.f;
    float xi = xbase[0], xf = xbase[256], xg = xbase[512], xo = xbase[768];

    for (int t = 0; t < TT; t++) {
        ulonglong2 ai, af, ag, ao;
        ai.x = ai.y = af.x = af.y = 0ull;
        ag.x = ag.y = ao.x = ao.y = 0ull;

#pragma unroll 4
        for (int kk = 0; kk < HDIM; kk += 8) {
            ulonglong2 h0 = *(const ulonglong2*)(hr + kk);       // h[kk..kk+3]
            ulonglong2 h1 = *(const ulonglong2*)(hr + kk + 4);   // h[kk+4..kk+7]
            ulonglong2 w;
            w = *(const ulonglong2*)(wi + kk);     ai.x = ffma2(h0.x, w.x, ai.x); ai.y = ffma2(h0.y, w.y, ai.y);
            w = *(const ulonglong2*)(wi + kk + 4); ai.x = ffma2(h1.x, w.x, ai.x); ai.y = ffma2(h1.y, w.y, ai.y);
            w = *(const ulonglong2*)(wf + kk);     af.x = ffma2(h0.x, w.x, af.x); af.y = ffma2(h0.y, w.y, af.y);
            w = *(const ulonglong2*)(wf + kk + 4); af.x = ffma2(h1.x, w.x, af.x); af.y = ffma2(h1.y, w.y, af.y);
            w = *(const ulonglong2*)(wg + kk);     ag.x = ffma2(h0.x, w.x, ag.x); ag.y = ffma2(h0.y, w.y, ag.y);
            w = *(const ulonglong2*)(wg + kk + 4); ag.x = ffma2(h1.x, w.x, ag.x); ag.y = ffma2(h1.y, w.y, ag.y);
            w = *(const ulonglong2*)(wo + kk);     ao.x = ffma2(h0.x, w.x, ao.x); ao.y = ffma2(h0.y, w.y, ao.y);
            w = *(const ulonglong2*)(wo + kk + 4); ao.x = ffma2(h1.x, w.x, ao.x); ao.y = ffma2(h1.y, w.y, ao.y);
        }

        float2 s0, s1;
        s0 = u2f2(ai.x); s1 = u2f2(ai.y);
        float gi = xi + s0.x + s0.y + s1.x + s1.y;
        s0 = u2f2(af.x); s1 = u2f2(af.y);
        float gf = xf + s0.x + s0.y + s1.x + s1.y;
        s0 = u2f2(ag.x); s1 = u2f2(ag.y);
        float gg = xg + s0.x + s0.y + s1.x + s1.y;
        s0 = u2f2(ao.x); s1 = u2f2(ao.y);
        float go = xo + s0.x + s0.y + s1.x + s1.y;

        c_st = sigf(gf) * c_st + sigf(gi) * tanhf(gg);
        float hn = sigf(go) * tanhf(c_st);
        houtb[(size_t)t * HDIM] = hn;

        if (t + 1 < TT) {
            const float* xr = xbase + (size_t)(t + 1) * G4;
            xi = xr[0]; xf = xr[256]; xg = xr[512]; xo = xr[768];

            __threadfence();
            __syncthreads();
            if (tid == 0) {
                int target = base + t + 1;
                int prev = atomicAdd(&g_count, 1);
                if (prev == GRID_P - 1) {
                    g_count = 0;
                    __threadfence();
                    g_flag = target;
                } else {
                    while (g_flag < target) { }
                }
                __threadfence();
            }
            __syncthreads();

            const float* src = hsrcb + (size_t)t * HDIM;
            float4 v0 = *(const float4*)src;
            float4 v1 = *(const float4*)(src + 4);
            *(float4*)(hsm + lrow * HS_STRIDE + lc0)     = v0;
            *(float4*)(hsm + lrow * HS_STRIDE + lc0 + 4) = v1;
            __syncthreads();
        }
    }
}

// =====================================================================
// Kernel 3: emissions (W_out cached in smem)
// =====================================================================
__global__ void emis_kernel(const int* __restrict__ lengths,
                            const float* __restrict__ W_out,
                            const float* __restrict__ b_out)
{
    __shared__ float Wsm[KTAG * 2 * HDIM];   // 40KB
    __shared__ float bsm[KTAG];

    const int tid = threadIdx.x;
    for (int i = tid; i < KTAG * 2 * HDIM; i += 256) Wsm[i] = W_out[i];
    if (tid < KTAG) bsm[tid] = b_out[tid];
    __syncthreads();

    const int warp = tid >> 5;
    const int lane = tid & 31;
    const int r = blockIdx.x * 8 + warp;
    const int b = r >> 9;
    const int t = r & 511;
    const int len = lengths[b];
    const int tr  = (t < len) ? (len - 1 - t) : t;

    const float* hf = g_h + (((size_t)0 * BB + b) * TT + t)  * HDIM;
    const float* hb = g_h + (((size_t)1 * BB + b) * TT + tr) * HDIM;

    float x[16];
#pragma unroll
    for (int i = 0; i < 8; i++) x[i]     = hf[lane + 32 * i];
#pragma unroll
    for (int i = 0; i < 8; i++) x[8 + i] = hb[lane + 32 * i];

    for (int kk = 0; kk < KTAG; kk++) {
        const float* w = Wsm + (size_t)kk * (2 * HDIM);
        float s = 0.f;
#pragma unroll
        for (int i = 0; i < 8; i++) s += x[i]     * w[lane + 32 * i];
#pragma unroll
        for (int i = 0; i < 8; i++) s += x[8 + i] * w[HDIM + lane + 32 * i];
#pragma unroll
        for (int off = 16; off; off >>= 1) s += __shfl_xor_sync(0xffffffffu, s, off);
        if (lane == 0) g_emis[((size_t)b * TT + t) * KTAG + kk] = s + bsm[kk];
    }
}

// =====================================================================
// Kernel 4: Viterbi. Emissions preloaded to smem; argmax via associative
// sortable-key 64-bit max (first-max semantics preserved exactly).
// =====================================================================
#define VIT_SMEM 53248

__global__ void viterbi_kernel(const int* __restrict__ lengths,
                               const int* __restrict__ stop_id_p,
                               const float* __restrict__ trans,
                               float* __restrict__ out)
{
    extern __shared__ char vsm[];
    float* emis_s = (float*)vsm;                 // 10240 floats
    float* tr     = emis_s + TT * KTAG;          // 400
    float* delta  = tr + KTAG * KTAG;            // 20
    float* term   = delta + KTAG;                // 20
    unsigned char* bp = (unsigned char*)(term + KTAG);  // 10240 bytes

    const int b = blockIdx.x;
    const int lane = threadIdx.x;

    for (int i = lane; i < TT * KTAG; i += 32)
        emis_s[i] = g_emis[(size_t)b * TT * KTAG + i];
    for (int i = lane; i < KTAG * KTAG; i += 32) tr[i] = trans[i];
    if (lane < KTAG) delta[lane] = 0.f;
    __syncwarp();

    const int len  = lengths[b];
    const int stop = *stop_id_p;

    for (int t = 0; t < TT; t++) {
        float nd = 0.f; int bpv = 0;
        if (lane < KTAG) {
            if (t < len) {
                const float* trl = tr + lane * KTAG;
                ull k0 = 0, k1 = 0, k2 = 0, k3 = 0;
#pragma unroll
                for (int p = 0; p < KTAG; p++) {
                    float s = delta[p] + trl[p];
                    int fi = __float_as_int(s);
                    unsigned u = (fi >= 0) ? ((unsigned)fi ^ 0x80000000u) : ~(unsigned)fi;
                    ull key = ((ull)u << 5) | (unsigned)(31 - p);
                    if ((p & 3) == 0)      k0 = (key > k0) ? key : k0;
                    else if ((p & 3) == 1) k1 = (key > k1) ? key : k1;
                    else if ((p & 3) == 2) k2 = (key > k2) ? key : k2;
                    else                   k3 = (key > k3) ? key : k3;
                }
                ull ka = (k0 > k1) ? k0 : k1;
                ull kb = (k2 > k3) ? k2 : k3;
                ull kc = (ka > kb) ? ka : kb;
                unsigned u = (unsigned)(kc >> 5);
                int arg = 31 - (int)(kc & 31);
                int fi = (u & 0x80000000u) ? (int)(u ^ 0x80000000u) : (int)~u;
                float best = __int_as_float(fi);
                nd  = best + emis_s[t * KTAG + lane];
                bpv = arg;
            } else {
                nd  = delta[lane];
                bpv = lane;
            }
        }
        __syncwarp();
        if (lane < KTAG) { delta[lane] = nd; bp[t * KTAG + lane] = (unsigned char)bpv; }
        __syncwarp();
    }

    if (lane < KTAG) term[lane] = delta[lane] + tr[stop * KTAG + lane];
    __syncwarp();

    if (lane == 0) {
        float best = -3.4e38f; int arg = 0;
        for (int j = 0; j < KTAG; j++)
            if (term[j] > best) { best = term[j]; arg = j; }
        out[b] = best;
        float* po = out + BB + (size_t)b * (TT + 1);
        po[TT] = (float)arg;
        int tag = arg;
        for (int t = TT - 1; t >= 0; t--) {
            tag = bp[t * KTAG + tag];
            po[t] = (float)tag;
        }
    }
}

// =====================================================================
// launch
// =====================================================================
extern "C" void kernel_launch(void* const* d_in, const int* in_sizes, int n_in,
                              void* d_out, int out_size)
{
    (void)in_sizes; (void)n_in; (void)out_size;
    const int*   sentence = (const int*)d_in[0];
    const int*   lengths  = (const int*)d_in[1];
    const int*   stop_id  = (const int*)d_in[3];
    const float* emb      = (const float*)d_in[4];
    const float* Wf_ih    = (const float*)d_in[5];
    const float* Wf_hh    = (const float*)d_in[6];
    const float* bf       = (const float*)d_in[7];
    const float* Wb_ih    = (const float*)d_in[8];
    const float* Wb_hh    = (const float*)d_in[9];
    const float* bb       = (const float*)d_in[10];
    const float* W_out    = (const float*)d_in[11];
    const float* b_out    = (const float*)d_in[12];
    const float* trans    = (const float*)d_in[13];
    float* out = (float*)d_out;

    static int attr_set = 0;
    if (!attr_set) {
        cudaFuncSetAttribute(lstm_persistent_kernel,
                             cudaFuncAttributeMaxDynamicSharedMemorySize, SMEM_LSTM);
        cudaFuncSetAttribute(viterbi_kernel,
                             cudaFuncAttributeMaxDynamicSharedMemorySize, VIT_SMEM);
        attr_set = 1;
    }

    dim3 g1(BB * TT / BM, G4 / BN, 2);
    gates_gemm_kernel<<<g1, 256>>>(sentence, lengths, emb, Wf_ih, bf, Wb_ih, bb);

    lstm_persistent_kernel<<<GRID_P, 256, SMEM_LSTM>>>(Wf_hh, Wb_hh);

    emis_kernel<<<BB * TT / 8, 256>>>(lengths, W_out, b_out);

    viterbi_kernel<<<BB, 32, VIT_SMEM>>>(lengths, stop_id, trans, out);
}